// round 2
// baseline (speedup 1.0000x reference)
#include <cuda_runtime.h>

// Scratch in __device__ globals (no allocation allowed).
// g_partials: each block overwrites its own slot every launch -> no reset needed.
// g_ticket:   atomicInc with limit gridDim-1 wraps back to 0 after exactly
//             gridDim increments per launch -> self-resetting, deterministic
//             across graph replays.
__device__ int          g_partials[4096];
__device__ unsigned int g_ticket = 0;

// One warp per note (note segments are contiguous; seg == 32 here so each lane
// does exactly one coalesced load per track). Reduce the DIFFERENCE of the two
// tracks (one shuffle chain instead of two), compare |sum_diff| > 0.5*count
// (no division), count qualifying warps per block with __syncthreads_count,
// and let the last block to finish reduce the per-block partials and write the
// final loss. Single kernel launch, no atomics on the output, no zero-init pass.
__global__ void __launch_bounds__(1024, 1)
pitch_loss_kernel(const float* __restrict__ gen_f0,
                  const float* __restrict__ t_f0,
                  const int*   __restrict__ onset,
                  const int*   __restrict__ offset,
                  float*       __restrict__ out,
                  int N) {
    const int lane  = threadIdx.x & 31;
    const int warp  = threadIdx.x >> 5;
    const int gwarp = blockIdx.x * (blockDim.x >> 5) + warp;

    int hit = 0;
    if (gwarp < N) {
        int a = onset[gwarp];
        int b = offset[gwarp];

        float d = 0.0f;
        for (int i = a + lane; i < b; i += 32)
            d += gen_f0[i] - t_f0[i];

        #pragma unroll
        for (int o = 16; o > 0; o >>= 1)
            d += __shfl_down_sync(0xFFFFFFFFu, d, o);

        if (lane == 0)
            hit = (fabsf(d) > 0.5f * (float)(b - a)) ? 1 : 0;
    }

    // Per-block count of qualifying notes (only lane-0 threads can set hit).
    int blk_count = __syncthreads_count(hit);

    __shared__ int is_last;
    if (threadIdx.x == 0) {
        g_partials[blockIdx.x] = blk_count;
        __threadfence();  // order partial write before the ticket increment
        unsigned int t = atomicInc(&g_ticket, gridDim.x - 1);
        is_last = (t == gridDim.x - 1) ? 1 : 0;
    }
    __syncthreads();

    // Last block reduces all partials and writes the scalar loss.
    if (is_last && warp == 0) {
        int total = 0;
        for (unsigned int i = lane; i < gridDim.x; i += 32)
            total += *(volatile int*)&g_partials[i];

        #pragma unroll
        for (int o = 16; o > 0; o >>= 1)
            total += __shfl_down_sync(0xFFFFFFFFu, total, o);

        if (lane == 0)
            out[0] = (float)total / (float)N;
    }
}

extern "C" void kernel_launch(void* const* d_in, const int* in_sizes, int n_in,
                              void* d_out, int out_size) {
    const float* gen_f0 = (const float*)d_in[0];
    const float* t_f0   = (const float*)d_in[1];
    const int*   onset  = (const int*)d_in[2];
    const int*   offset = (const int*)d_in[3];
    float* out = (float*)d_out;

    int N = in_sizes[2];                      // number of notes (1024)

    const int THREADS = 1024;                 // 32 warps per block
    int blocks = (N + 31) / 32;               // one warp per note -> 32 blocks
    pitch_loss_kernel<<<blocks, THREADS>>>(gen_f0, t_f0, onset, offset, out, N);
}